// round 1
// baseline (speedup 1.0000x reference)
#include <cuda_runtime.h>

#define NROW 1024      // rows of a and of b
#define KDIM 2048      // inner dim of stage 1
#define NF   128       // number of feature rows

// Stage-1 outputs, stored TRANSPOSED (k-major for stage 2): [NF][NROW]
__device__ float g_afk[NF * NROW];
__device__ float g_bfk[NF * NROW];

// ---------------------------------------------------------------------------
// Stage 1:  C_T[n][m] = relu( sum_k feats[n][k] * X[m][k] )
// X = a (rows 0..1023) or b (rows 1024..2047), selected per block.
// Block tile: 32 n x 64 m, BK = 32.  grid = (2048/64, 128/32) = (32, 4).
// 256 threads: ty = t/32 (n-group of 4), tx = t%32 (m-group of 2).
// ---------------------------------------------------------------------------
__global__ __launch_bounds__(256, 2) void stage1_kernel(
    const float* __restrict__ a,
    const float* __restrict__ b,
    const float* __restrict__ feats)
{
    __shared__ float sF[32][36];   // [n][k], +4 pad keeps float4 stores aligned
    __shared__ float sX[32][66];   // [k][m], +2 pad reduces transpose-store conflicts

    const int t  = threadIdx.x;
    const int tx = t & 31;          // m group (2 outputs)
    const int ty = t >> 5;          // n group (4 outputs)

    const int m_tile = blockIdx.x * 64;       // 0..1984 over stacked [a;b]
    const int n_tile = blockIdx.y * 32;

    const bool  is_a   = (m_tile < NROW);
    const float* X     = is_a ? a : b;
    const int   m_base = is_a ? m_tile : (m_tile - NROW);

    // gmem load mapping
    const int lf_n = t >> 3;             // 0..31
    const int lf_k = (t & 7) << 2;       // 0,4,...,28
    const int lx_m = t >> 3;             // 0..31 (second chunk +32)
    const int lx_k = (t & 7) << 2;

    float acc[4][2];
    #pragma unroll
    for (int i = 0; i < 4; i++) { acc[i][0] = 0.f; acc[i][1] = 0.f; }

    for (int k0 = 0; k0 < KDIM; k0 += 32) {
        // feats tile: row-major, float4 store
        float4 f4 = *(const float4*)&feats[(n_tile + lf_n) * KDIM + k0 + lf_k];
        *(float4*)&sF[lf_n][lf_k] = f4;

        // X tile: transpose into k-major
        #pragma unroll
        for (int r = 0; r < 2; r++) {
            int m = lx_m + r * 32;
            float4 x4 = *(const float4*)&X[(m_base + m) * KDIM + k0 + lx_k];
            sX[lx_k + 0][m] = x4.x;
            sX[lx_k + 1][m] = x4.y;
            sX[lx_k + 2][m] = x4.z;
            sX[lx_k + 3][m] = x4.w;
        }
        __syncthreads();

        #pragma unroll
        for (int kk = 0; kk < 32; kk++) {
            float f0 = sF[ty * 4 + 0][kk];   // broadcast within warp
            float f1 = sF[ty * 4 + 1][kk];
            float f2 = sF[ty * 4 + 2][kk];
            float f3 = sF[ty * 4 + 3][kk];
            float2 xv = *(const float2*)&sX[kk][tx * 2];
            acc[0][0] += f0 * xv.x;  acc[0][1] += f0 * xv.y;
            acc[1][0] += f1 * xv.x;  acc[1][1] += f1 * xv.y;
            acc[2][0] += f2 * xv.x;  acc[2][1] += f2 * xv.y;
            acc[3][0] += f3 * xv.x;  acc[3][1] += f3 * xv.y;
        }
        __syncthreads();
    }

    float* dst = is_a ? g_afk : g_bfk;
    #pragma unroll
    for (int i = 0; i < 4; i++) {
        int n = n_tile + ty * 4 + i;
        float2 v;
        v.x = fmaxf(acc[i][0], 0.f);
        v.y = fmaxf(acc[i][1], 0.f);
        *(float2*)&dst[n * NROW + m_base + tx * 2] = v;   // coalesced
    }
}

// ---------------------------------------------------------------------------
// Stage 2:  out[i][j] = sum_k g_afk[k][i] * g_bfk[k][j]   (K = 128)
// Both operands are k-major in gmem -> no smem transpose needed.
// Block tile 64x64, two 64-k chunks (smem = 2 * 16 KB * 2 = 32 KB static).
// 256 threads: ty = t/16 over i (4 outputs), tx = t%16 over j (4 outputs).
// grid = (16, 16).
// ---------------------------------------------------------------------------
__global__ __launch_bounds__(256, 2) void stage2_kernel(float* __restrict__ out)
{
    __shared__ float sA[64][64];   // [k][i]
    __shared__ float sB[64][64];   // [k][j]

    const int t  = threadIdx.x;
    const int tx = t & 15;
    const int ty = t >> 4;
    const int i_tile = blockIdx.y * 64;
    const int j_tile = blockIdx.x * 64;

    float acc[4][4];
    #pragma unroll
    for (int i = 0; i < 4; i++)
        #pragma unroll
        for (int j = 0; j < 4; j++) acc[i][j] = 0.f;

    for (int kb = 0; kb < NF; kb += 64) {
        #pragma unroll
        for (int r = 0; r < 4; r++) {
            int idx = t + 256 * r;
            int k = idx >> 4;             // 0..63
            int q = (idx & 15) << 2;      // 0..60
            *(float4*)&sA[k][q] = *(const float4*)&g_afk[(kb + k) * NROW + i_tile + q];
            *(float4*)&sB[k][q] = *(const float4*)&g_bfk[(kb + k) * NROW + j_tile + q];
        }
        __syncthreads();

        #pragma unroll
        for (int k = 0; k < 64; k++) {
            float4 ra = *(const float4*)&sA[k][ty * 4];   // 2-addr broadcast in warp
            float4 rb = *(const float4*)&sB[k][tx * 4];   // conflict-free per phase
            acc[0][0] += ra.x * rb.x;  acc[0][1] += ra.x * rb.y;
            acc[0][2] += ra.x * rb.z;  acc[0][3] += ra.x * rb.w;
            acc[1][0] += ra.y * rb.x;  acc[1][1] += ra.y * rb.y;
            acc[1][2] += ra.y * rb.z;  acc[1][3] += ra.y * rb.w;
            acc[2][0] += ra.z * rb.x;  acc[2][1] += ra.z * rb.y;
            acc[2][2] += ra.z * rb.z;  acc[2][3] += ra.z * rb.w;
            acc[3][0] += ra.w * rb.x;  acc[3][1] += ra.w * rb.y;
            acc[3][2] += ra.w * rb.z;  acc[3][3] += ra.w * rb.w;
        }
        __syncthreads();
    }

    #pragma unroll
    for (int i = 0; i < 4; i++) {
        float4 v = make_float4(acc[i][0], acc[i][1], acc[i][2], acc[i][3]);
        *(float4*)&out[(i_tile + ty * 4 + i) * NROW + j_tile + tx * 4] = v;
    }
}

// ---------------------------------------------------------------------------
extern "C" void kernel_launch(void* const* d_in, const int* in_sizes, int n_in,
                              void* d_out, int out_size)
{
    (void)in_sizes; (void)n_in; (void)out_size;
    const float* a     = (const float*)d_in[0];
    const float* b     = (const float*)d_in[1];
    const float* feats = (const float*)d_in[2];
    float* out = (float*)d_out;

    stage1_kernel<<<dim3(32, 4), 256>>>(a, b, feats);
    stage2_kernel<<<dim3(16, 16), 256>>>(out);
}

// round 4
// speedup vs baseline: 2.7408x; 2.7408x over previous
#include <cuda_runtime.h>
#include <cuda_fp16.h>
#include <cstdint>

#define NROW 1024
#define KDIM 2048
#define NF   128
#define SPLITK 8
#define KCHUNK (KDIM / SPLITK)   // 256
#define BK 64

// ---------------------------------------------------------------------------
// Device scratch
// ---------------------------------------------------------------------------
__device__ __half g_fhi16[NF * KDIM];            // feats hi (fp16)
__device__ __half g_flo16[NF * KDIM];            // feats lo (fp16)
__device__ float  g_part[SPLITK * 2048 * NF];    // split-K partials [ks][m][n]
__device__ __half g_shi[2048 * NF];              // relu(scores) hi, [m][k]
__device__ __half g_slo[2048 * NF];              // relu(scores) lo, [m][k]

// ---------------------------------------------------------------------------
// Helpers
// ---------------------------------------------------------------------------
__device__ __forceinline__ uint32_t su32(const void* p) {
    return (uint32_t)__cvta_generic_to_shared(p);
}
__device__ __forceinline__ uint32_t pk(__half a, __half b) {
    __half2 h = __halves2half2(a, b);
    return *reinterpret_cast<uint32_t*>(&h);
}
__device__ __forceinline__ void cp16(uint32_t dst, const void* src) {
    asm volatile("cp.async.ca.shared.global [%0], [%1], 16;" :: "r"(dst), "l"(src));
}

#define CP_COMMIT() asm volatile("cp.async.commit_group;" ::: "memory")
#define CP_WAIT0()  asm volatile("cp.async.wait_group 0;"  ::: "memory")

#define LDSM4(R, addr) \
    asm volatile("ldmatrix.sync.aligned.m8n8.x4.shared.b16 {%0,%1,%2,%3}, [%4];" \
        : "=r"((R)[0]), "=r"((R)[1]), "=r"((R)[2]), "=r"((R)[3]) : "r"(addr))

#define MMA(C, A, b0, b1) \
    asm volatile("mma.sync.aligned.m16n8k16.row.col.f32.f16.f16.f32 " \
        "{%0,%1,%2,%3}, {%4,%5,%6,%7}, {%8,%9}, {%0,%1,%2,%3};" \
        : "+f"((C)[0]), "+f"((C)[1]), "+f"((C)[2]), "+f"((C)[3]) \
        : "r"((A)[0]), "r"((A)[1]), "r"((A)[2]), "r"((A)[3]), "r"(b0), "r"(b1))

// swizzled byte offset, 128B rows (64 halves): kh = half index (mult of 8 here)
__device__ __forceinline__ uint32_t swz1(int row, int kh) {
    return (uint32_t)(row * 128 + ((((kh >> 3) ^ (row & 7)) << 4)));
}
// swizzled byte offset, 256B rows (128 halves): chunk c = kh>>3 in 0..15
__device__ __forceinline__ uint32_t swz2(int row, int kh) {
    int c = kh >> 3;
    return (uint32_t)(row * 256 + ((((c & 8) | ((c ^ (row & 7)) & 7)) << 4)));
}

// ---------------------------------------------------------------------------
// Prep: feats fp32 -> fp16 hi/lo (row-major [NF][KDIM])
// ---------------------------------------------------------------------------
__global__ void prep_feats(const float* __restrict__ f) {
    int g = blockIdx.x * blockDim.x + threadIdx.x;   // 0..16383
    #pragma unroll
    for (int j = 0; j < 4; j++) {
        size_t base = (size_t)g * 16 + j * 4;
        float4 v = *(const float4*)&f[base];
        __half h0 = __float2half_rn(v.x), h1 = __float2half_rn(v.y);
        __half h2 = __float2half_rn(v.z), h3 = __float2half_rn(v.w);
        __half l0 = __float2half_rn(v.x - __half2float(h0));
        __half l1 = __float2half_rn(v.y - __half2float(h1));
        __half l2 = __float2half_rn(v.z - __half2float(h2));
        __half l3 = __float2half_rn(v.w - __half2float(h3));
        uint2 hw; hw.x = pk(h0, h1); hw.y = pk(h2, h3);
        uint2 lw; lw.x = pk(l0, l1); lw.y = pk(l2, l3);
        *(uint2*)&g_fhi16[base] = hw;
        *(uint2*)&g_flo16[base] = lw;
    }
}

// ---------------------------------------------------------------------------
// Stage 1: g_part[ks][m 128-tile][0..127] = X[m, kchunk] . feats^T  (3-term fp16)
// grid (16, 8), 256 threads. smem: 2 x 64KB buffers:
//   XHI +0 (16KB), XLO +16384, FHI +32768, FLO +49152
// ---------------------------------------------------------------------------
__global__ __launch_bounds__(256, 1) void stage1(const float* __restrict__ A_,
                                                 const float* __restrict__ B_) {
    extern __shared__ char smem[];
    const uint32_t sb = su32(smem);
    const int t = threadIdx.x, lane = t & 31, wid = t >> 5;
    const int m0 = blockIdx.x * 128;
    const int ks = blockIdx.y;
    const float* X = (m0 < NROW) ? A_ : B_;
    const int mb = (m0 < NROW) ? m0 : m0 - NROW;
    const int kbase = ks * KCHUNK;

    const int wy = wid & 1, wx = wid >> 1;
    const int m0w = wy * 64, n0w = wx * 32;

    const int aRow = lane & 15, aK = (lane >> 4) << 3;
    const int bN = ((lane >> 4) << 3) + (lane & 7), bK = ((lane >> 3) & 1) << 3;

    float acc[4][4][4];
    #pragma unroll
    for (int i = 0; i < 4; i++)
        #pragma unroll
        for (int j = 0; j < 4; j++)
            #pragma unroll
            for (int q = 0; q < 4; q++) acc[i][j][q] = 0.f;

    float xr[4][8];

    // ---- slab 0 prologue ----
    {
        const int kk = kbase;
        #pragma unroll
        for (int i = 0; i < 4; i++) {
            int chunk = t + i * 256; int row = chunk >> 3, c = chunk & 7;
            uint32_t off = (uint32_t)(row * 128 + (((c ^ (row & 7)) << 4)));
            cp16(sb + 32768 + off, &g_fhi16[row * KDIM + kk + c * 8]);
            cp16(sb + 49152 + off, &g_flo16[row * KDIM + kk + c * 8]);
            const float* src = &X[(size_t)(mb + row) * KDIM + kk + c * 8];
            *(float4*)&xr[i][0] = *(const float4*)src;
            *(float4*)&xr[i][4] = *(const float4*)(src + 4);
        }
        CP_COMMIT();
        #pragma unroll
        for (int i = 0; i < 4; i++) {
            int chunk = t + i * 256; int row = chunk >> 3, c = chunk & 7;
            uint32_t off = (uint32_t)(row * 128 + (((c ^ (row & 7)) << 4)));
            uint32_t hi[4], lo[4];
            #pragma unroll
            for (int j = 0; j < 4; j++) {
                float f0 = xr[i][j * 2], f1 = xr[i][j * 2 + 1];
                __half h0 = __float2half_rn(f0), h1 = __float2half_rn(f1);
                __half l0 = __float2half_rn(f0 - __half2float(h0));
                __half l1 = __float2half_rn(f1 - __half2float(h1));
                hi[j] = pk(h0, h1); lo[j] = pk(l0, l1);
            }
            *(uint4*)(smem + off)         = make_uint4(hi[0], hi[1], hi[2], hi[3]);
            *(uint4*)(smem + 16384 + off) = make_uint4(lo[0], lo[1], lo[2], lo[3]);
        }
        CP_WAIT0();
        __syncthreads();
    }

    // ---- main loop over 4 slabs ----
    #pragma unroll 1
    for (int s = 0; s < 4; s++) {
        const int p = s & 1, np = p ^ 1;
        if (s < 3) {
            const int kk = kbase + (s + 1) * BK;
            uint32_t nb = sb + np * 65536;
            #pragma unroll
            for (int i = 0; i < 4; i++) {
                int chunk = t + i * 256; int row = chunk >> 3, c = chunk & 7;
                uint32_t off = (uint32_t)(row * 128 + (((c ^ (row & 7)) << 4)));
                cp16(nb + 32768 + off, &g_fhi16[row * KDIM + kk + c * 8]);
                cp16(nb + 49152 + off, &g_flo16[row * KDIM + kk + c * 8]);
                const float* src = &X[(size_t)(mb + row) * KDIM + kk + c * 8];
                *(float4*)&xr[i][0] = *(const float4*)src;
                *(float4*)&xr[i][4] = *(const float4*)(src + 4);
            }
            CP_COMMIT();
        }

        // compute on buffer p
        const uint32_t base = sb + p * 65536;
        #pragma unroll
        for (int k16 = 0; k16 < 4; k16++) {
            const int kh = k16 * 16;
            uint32_t ah[4][4], al[4][4], bh[2][4], bl[2][4];
            #pragma unroll
            for (int mt = 0; mt < 4; mt++) {
                uint32_t ra = base + swz1(m0w + mt * 16 + aRow, kh + aK);
                LDSM4(ah[mt], ra);
                LDSM4(al[mt], ra + 16384);
            }
            #pragma unroll
            for (int g = 0; g < 2; g++) {
                uint32_t rb = base + 32768 + swz1(n0w + g * 16 + bN, kh + bK);
                LDSM4(bh[g], rb);
                LDSM4(bl[g], rb + 16384);
            }
            #pragma unroll
            for (int mt = 0; mt < 4; mt++)
                #pragma unroll
                for (int nt = 0; nt < 4; nt++) {
                    uint32_t h0 = bh[nt >> 1][(nt & 1) * 2], h1 = bh[nt >> 1][(nt & 1) * 2 + 1];
                    uint32_t l0 = bl[nt >> 1][(nt & 1) * 2], l1 = bl[nt >> 1][(nt & 1) * 2 + 1];
                    MMA(acc[mt][nt], ah[mt], h0, h1);
                    MMA(acc[mt][nt], ah[mt], l0, l1);
                    MMA(acc[mt][nt], al[mt], h0, h1);
                }
        }

        if (s < 3) {
            const uint32_t nboff = (uint32_t)(np * 65536);
            #pragma unroll
            for (int i = 0; i < 4; i++) {
                int chunk = t + i * 256; int row = chunk >> 3, c = chunk & 7;
                uint32_t off = nboff + (uint32_t)(row * 128 + (((c ^ (row & 7)) << 4)));
                uint32_t hi[4], lo[4];
                #pragma unroll
                for (int j = 0; j < 4; j++) {
                    float f0 = xr[i][j * 2], f1 = xr[i][j * 2 + 1];
                    __half h0 = __float2half_rn(f0), h1 = __float2half_rn(f1);
                    __half l0 = __float2half_rn(f0 - __half2float(h0));
                    __half l1 = __float2half_rn(f1 - __half2float(h1));
                    hi[j] = pk(h0, h1); lo[j] = pk(l0, l1);
                }
                *(uint4*)(smem + off)         = make_uint4(hi[0], hi[1], hi[2], hi[3]);
                *(uint4*)(smem + 16384 + off) = make_uint4(lo[0], lo[1], lo[2], lo[3]);
            }
            CP_WAIT0();
        }
        __syncthreads();
    }

    // ---- epilogue: fp32 partials ----
    float* dst = g_part + (size_t)ks * (2048 * NF);
    #pragma unroll
    for (int mt = 0; mt < 4; mt++)
        #pragma unroll
        for (int nt = 0; nt < 4; nt++) {
            int r = m0 + m0w + mt * 16 + (lane >> 2);
            int cc = n0w + nt * 8 + (lane & 3) * 2;
            *(float2*)&dst[(size_t)r * NF + cc] =
                make_float2(acc[mt][nt][0], acc[mt][nt][1]);
            *(float2*)&dst[(size_t)(r + 8) * NF + cc] =
                make_float2(acc[mt][nt][2], acc[mt][nt][3]);
        }
}

// ---------------------------------------------------------------------------
// Reduce: sum split-K partials, relu, split fp16 hi/lo into [m][k] k-contig
// ---------------------------------------------------------------------------
__global__ void reduce_relu() {
    int g = blockIdx.x * blockDim.x + threadIdx.x;   // 0..65535
    size_t o = (size_t)g * 4;
    float4 s = make_float4(0.f, 0.f, 0.f, 0.f);
    #pragma unroll
    for (int p = 0; p < SPLITK; p++) {
        float4 v = *(const float4*)&g_part[(size_t)p * (2048 * NF) + o];
        s.x += v.x; s.y += v.y; s.z += v.z; s.w += v.w;
    }
    s.x = fmaxf(s.x, 0.f); s.y = fmaxf(s.y, 0.f);
    s.z = fmaxf(s.z, 0.f); s.w = fmaxf(s.w, 0.f);
    __half h0 = __float2half_rn(s.x), h1 = __float2half_rn(s.y);
    __half h2 = __float2half_rn(s.z), h3 = __float2half_rn(s.w);
    __half l0 = __float2half_rn(s.x - __half2float(h0));
    __half l1 = __float2half_rn(s.y - __half2float(h1));
    __half l2 = __float2half_rn(s.z - __half2float(h2));
    __half l3 = __float2half_rn(s.w - __half2float(h3));
    uint2 hw; hw.x = pk(h0, h1); hw.y = pk(h2, h3);
    uint2 lw; lw.x = pk(l0, l1); lw.y = pk(l2, l3);
    *(uint2*)&g_shi[o] = hw;
    *(uint2*)&g_slo[o] = lw;
}

// ---------------------------------------------------------------------------
// Stage 2: out[i][j] = sum_k shi/slo[i][k] * shi/slo[1024+j][k]  (3-term)
// grid (16, 8): CTA 128 i x 64 j. smem single buffer 96KB:
//   AHI +0 (32KB), ALO +32768, BHI +65536 (16KB), BLO +81920
// ---------------------------------------------------------------------------
__global__ __launch_bounds__(256, 1) void stage2(float* __restrict__ out) {
    extern __shared__ char smem[];
    const uint32_t sb = su32(smem);
    const int t = threadIdx.x, lane = t & 31, wid = t >> 5;
    const int it = blockIdx.y * 128, jt = blockIdx.x * 64;
    const int wy = wid & 3, wx = wid >> 2;
    const int m0w = wy * 32, n0w = wx * 32;

    #pragma unroll
    for (int i = 0; i < 8; i++) {
        int idx = t + i * 256; int row = idx >> 4, c = idx & 15;
        uint32_t off = swz2(row, c * 8);
        *(uint4*)(smem + off)         = *(const uint4*)&g_shi[(size_t)(it + row) * NF + c * 8];
        *(uint4*)(smem + 32768 + off) = *(const uint4*)&g_slo[(size_t)(it + row) * NF + c * 8];
    }
    #pragma unroll
    for (int i = 0; i < 4; i++) {
        int idx = t + i * 256; int row = idx >> 4, c = idx & 15;
        uint32_t off = swz2(row, c * 8);
        *(uint4*)(smem + 65536 + off) = *(const uint4*)&g_shi[(size_t)(1024 + jt + row) * NF + c * 8];
        *(uint4*)(smem + 81920 + off) = *(const uint4*)&g_slo[(size_t)(1024 + jt + row) * NF + c * 8];
    }
    __syncthreads();

    const int aRow = lane & 15, aK = (lane >> 4) << 3;
    const int bN = ((lane >> 4) << 3) + (lane & 7), bK = ((lane >> 3) & 1) << 3;

    float acc[2][4][4];
    #pragma unroll
    for (int i = 0; i < 2; i++)
        #pragma unroll
        for (int j = 0; j < 4; j++)
            #pragma unroll
            for (int q = 0; q < 4; q++) acc[i][j][q] = 0.f;

    #pragma unroll
    for (int k16 = 0; k16 < 8; k16++) {
        const int kh = k16 * 16;
        uint32_t ah[2][4], al[2][4], bh[2][4], bl[2][4];
        #pragma unroll
        for (int mt = 0; mt < 2; mt++) {
            uint32_t ra = sb + swz2(m0w + mt * 16 + aRow, kh + aK);
            LDSM4(ah[mt], ra);
            LDSM4(al[mt], ra + 32768);
        }
        #pragma unroll
        for (int g = 0; g < 2; g++) {
            uint32_t rb = sb + 65536 + swz2(n0w + g * 16 + bN, kh + bK);
            LDSM4(bh[g], rb);
            LDSM4(bl[g], rb + 16384);
        }
        #pragma unroll
        for (int mt = 0; mt < 2; mt++)
            #pragma unroll
            for (int nt = 0; nt < 4; nt++) {
                uint32_t h0 = bh[nt >> 1][(nt & 1) * 2], h1 = bh[nt >> 1][(nt & 1) * 2 + 1];
                uint32_t l0 = bl[nt >> 1][(nt & 1) * 2], l1 = bl[nt >> 1][(nt & 1) * 2 + 1];
                MMA(acc[mt][nt], ah[mt], h0, h1);
                MMA(acc[mt][nt], ah[mt], l0, l1);
                MMA(acc[mt][nt], al[mt], h0, h1);
            }
    }

    #pragma unroll
    for (int mt = 0; mt < 2; mt++)
        #pragma unroll
        for (int nt = 0; nt < 4; nt++) {
            int r = it + m0w + mt * 16 + (lane >> 2);
            int cc = jt + n0w + nt * 8 + (lane & 3) * 2;
            *(float2*)&out[(size_t)r * NROW + cc] =
                make_float2(acc[mt][nt][0], acc[mt][nt][1]);
            *(float2*)&out[(size_t)(r + 8) * NROW + cc] =
                make_float2(acc[mt][nt][2], acc[mt][nt][3]);
        }
}

// ---------------------------------------------------------------------------
extern "C" void kernel_launch(void* const* d_in, const int* in_sizes, int n_in,
                              void* d_out, int out_size) {
    (void)in_sizes; (void)n_in; (void)out_size;
    const float* a = (const float*)d_in[0];
    const float* b = (const float*)d_in[1];
    const float* f = (const float*)d_in[2];
    float* out = (float*)d_out;

    cudaFuncSetAttribute(stage1, cudaFuncAttributeMaxDynamicSharedMemorySize, 131072);
    cudaFuncSetAttribute(stage2, cudaFuncAttributeMaxDynamicSharedMemorySize, 98304);

    prep_feats<<<64, 256>>>(f);
    stage1<<<dim3(16, SPLITK), 256, 131072>>>(a, b);
    reduce_relu<<<256, 256>>>();
    stage2<<<dim3(16, 8), 256, 98304>>>(out);
}